// round 1
// baseline (speedup 1.0000x reference)
#include <cuda_runtime.h>

// Problem constants
#define BB  16
#define MM  128
#define NH  256
#define EH  128
#define KH  640              // 2*NH + EH
#define RR  (BB * MM)        // 2048 rows

// Scratch (no allocs allowed -> __device__ globals)
__device__ float g_AtX[RR * NH];     // A^T @ X            [2048,256]
__device__ float g_sA [RR];          // column sums of A   [2048]
__device__ float g_aggE[RR * EH];    // sum_i A*E          [2048,128]
__device__ float g_h  [RR * KH];     // relu'd concat h    [2048,640]

// ---------------------------------------------------------------------------
// K1: AtX[r,d] = sum_i A[b,i,j] * X[b,i,d],  sA[r] = sum_i A[b,i,j]
//     r = b*128 + j.  grid=2048, block=256 (thread = d)
// ---------------------------------------------------------------------------
__global__ void k_atx(const float* __restrict__ A, const float* __restrict__ X) {
    int r = blockIdx.x;
    int b = r >> 7, j = r & 127;
    __shared__ float Ac[MM];
    int t = threadIdx.x;
    if (t < MM) Ac[t] = A[(b * MM + t) * MM + j];
    __syncthreads();

    const float* Xb = X + (size_t)b * MM * NH;
    float a0 = 0.f, a1 = 0.f, a2 = 0.f, a3 = 0.f;
#pragma unroll
    for (int i = 0; i < MM; i += 4) {
        a0 += Ac[i + 0] * Xb[(i + 0) * NH + t];
        a1 += Ac[i + 1] * Xb[(i + 1) * NH + t];
        a2 += Ac[i + 2] * Xb[(i + 2) * NH + t];
        a3 += Ac[i + 3] * Xb[(i + 3) * NH + t];
    }
    g_AtX[r * NH + t] = (a0 + a1) + (a2 + a3);

    if (t == 0) {
        float s = 0.f;
#pragma unroll
        for (int i = 0; i < MM; i++) s += Ac[i];
        g_sA[r] = s;
    }
}

// ---------------------------------------------------------------------------
// K2: aggE[r,e] = sum_i A[b,i,j] * E[b,i,j,e]
//     Streams all 128 MB of E exactly once. grid=2048, block=128 (thread = e)
// ---------------------------------------------------------------------------
__global__ void k_agge(const float* __restrict__ A, const float* __restrict__ E) {
    int r = blockIdx.x;
    int b = r >> 7, j = r & 127;
    __shared__ float Ac[MM];
    int t = threadIdx.x;  // e index
    Ac[t] = A[(b * MM + t) * MM + j];
    __syncthreads();

    // E[b,i,j,e] = E + b*M*M*EH + i*M*EH + j*EH + e
    const float* Eb = E + ((size_t)b * MM * MM + j) * EH;
    float a0 = 0.f, a1 = 0.f, a2 = 0.f, a3 = 0.f;
#pragma unroll
    for (int i = 0; i < MM; i += 4) {
        a0 += Ac[i + 0] * Eb[(size_t)(i + 0) * MM * EH + t];
        a1 += Ac[i + 1] * Eb[(size_t)(i + 1) * MM * EH + t];
        a2 += Ac[i + 2] * Eb[(size_t)(i + 2) * MM * EH + t];
        a3 += Ac[i + 3] * Eb[(size_t)(i + 3) * MM * EH + t];
    }
    g_aggE[r * EH + t] = (a0 + a1) + (a2 + a3);
}

// ---------------------------------------------------------------------------
// K3: h[r, 384 + d] = relu(X[r,d])   (X part of the concat)
// ---------------------------------------------------------------------------
__global__ void k_hx(const float* __restrict__ X) {
    int idx = blockIdx.x * blockDim.x + threadIdx.x;  // 2048*256
    int r = idx >> 8, d = idx & 255;
    float v = X[idx];
    g_h[r * KH + 2 * NH - NH + NH + d - d + 384 + d - d] = 0.f; // (dead-code avoided below)
}

// (the line above was a slip guard; real implementation:)
__global__ void k_hx2(const float* __restrict__ X) {
    int idx = blockIdx.x * blockDim.x + threadIdx.x;  // 2048*256
    int r = idx >> 8, d = idx & 255;
    float v = X[idx];
    g_h[r * KH + 384 + d] = fmaxf(v, 0.f);
}

// ---------------------------------------------------------------------------
// Tiled SGEMM: C[r, colOff+n] = epilogue( sum_k Am[r,k]*W[k,n] )
//   MODE 0: v = relu(acc + sA[r]*bias[n])          -> writes into g_h slice
//   MODE 1: v = (acc + bias[n]) * scale[r]         -> final output
// BM=BN=64, BK=16, 256 threads, 4x4 per-thread microtile.
// Requires: rows % 64 == 0, Ndim % 64 == 0, Kdim % 16 == 0.
// ---------------------------------------------------------------------------
template <int MODE>
__global__ __launch_bounds__(256) void sgemm64(
    const float* __restrict__ Am, int Kdim,
    const float* __restrict__ W,  int Ndim,
    const float* __restrict__ bias,
    const float* __restrict__ scale,
    float* __restrict__ C, int ldc, int colOff)
{
    constexpr int BM = 64, BN = 64, BK = 16;
    __shared__ float As[BK][BM + 1];
    __shared__ float Bs[BK][BN];

    int tid = threadIdx.x;
    int rowBase = blockIdx.x * BM;
    int colBase = blockIdx.y * BN;

    int arow = tid >> 2;            // 0..63
    int acol = (tid & 3) << 2;      // 0,4,8,12
    int brow = tid >> 4;            // 0..15
    int bcol = (tid & 15) << 2;     // 0..60

    int tx = tid & 15, ty = tid >> 4;

    float acc[4][4] = {};

    for (int k0 = 0; k0 < Kdim; k0 += BK) {
        float4 av = *(const float4*)&Am[(size_t)(rowBase + arow) * Kdim + k0 + acol];
        As[acol + 0][arow] = av.x;
        As[acol + 1][arow] = av.y;
        As[acol + 2][arow] = av.z;
        As[acol + 3][arow] = av.w;
        float4 bv = *(const float4*)&W[(size_t)(k0 + brow) * Ndim + colBase + bcol];
        *(float4*)&Bs[brow][bcol] = bv;
        __syncthreads();

#pragma unroll
        for (int kk = 0; kk < BK; kk++) {
            float am[4], bn[4];
#pragma unroll
            for (int i = 0; i < 4; i++) am[i] = As[kk][ty * 4 + i];
#pragma unroll
            for (int i = 0; i < 4; i++) bn[i] = Bs[kk][tx * 4 + i];
#pragma unroll
            for (int i = 0; i < 4; i++)
#pragma unroll
                for (int jj = 0; jj < 4; jj++)
                    acc[i][jj] += am[i] * bn[jj];
        }
        __syncthreads();
    }

#pragma unroll
    for (int i = 0; i < 4; i++) {
        int r = rowBase + ty * 4 + i;
        float sc = scale[r];
#pragma unroll
        for (int jj = 0; jj < 4; jj++) {
            int n = colBase + tx * 4 + jj;
            float v = acc[i][jj];
            if (MODE == 0) {
                v += sc * bias[n];
                v = fmaxf(v, 0.f);
            } else {
                v = (v + bias[n]) * sc;
            }
            C[(size_t)r * ldc + colOff + n] = v;
        }
    }
}

// ---------------------------------------------------------------------------
extern "C" void kernel_launch(void* const* d_in, const int* in_sizes, int n_in,
                              void* d_out, int out_size) {
    const float* X    = (const float*)d_in[0];
    const float* E    = (const float*)d_in[1];
    const float* A    = (const float*)d_in[2];
    const float* w    = (const float*)d_in[3];
    const float* Wv_w = (const float*)d_in[4];
    const float* Wv_b = (const float*)d_in[5];
    const float* We_w = (const float*)d_in[6];
    const float* We_b = (const float*)d_in[7];
    const float* Wu_w = (const float*)d_in[8];
    const float* Wu_b = (const float*)d_in[9];
    float* out = (float*)d_out;

    float *p_AtX, *p_sA, *p_aggE, *p_h;
    cudaGetSymbolAddress((void**)&p_AtX,  g_AtX);
    cudaGetSymbolAddress((void**)&p_sA,   g_sA);
    cudaGetSymbolAddress((void**)&p_aggE, g_aggE);
    cudaGetSymbolAddress((void**)&p_h,    g_h);

    // Independent producers
    k_atx <<<RR, 256>>>(A, X);
    k_agge<<<RR, 128>>>(A, E);
    k_hx2 <<<RR, 256>>>(X);

    // h[:, 0:256] = relu(AtX @ Wv_w + sA*Wv_b)
    {
        dim3 grid(RR / 64, NH / 64);
        sgemm64<0><<<grid, 256>>>(p_AtX, NH, Wv_w, NH, Wv_b, p_sA, p_h, KH, 0);
    }
    // h[:, 256:384] = relu(aggE @ We_w + sA*We_b)
    {
        dim3 grid(RR / 64, EH / 64);
        sgemm64<0><<<grid, 256>>>(p_aggE, EH, We_w, EH, We_b, p_sA, p_h, KH, NH);
    }
    // out = (h @ Wu_w + Wu_b) * w
    {
        dim3 grid(RR / 64, NH / 64);
        sgemm64<1><<<grid, 256>>>(p_h, KH, Wu_w, NH, Wu_b, w, out, NH, 0);
    }
}

// round 2
// speedup vs baseline: 1.6038x; 1.6038x over previous
#include <cuda_runtime.h>

#define BB 16
#define MM 128
#define NH 256
#define EH 128
#define HW 384              // h scratch width: agg_node(256) + agg_edge(128)
#define RR (BB*MM)          // 2048

__device__ float g_AtX[RR * NH];
__device__ float g_sA [RR];
__device__ float g_aggE[RR * EH];
__device__ float g_h  [RR * HW];

// ---------------------------------------------------------------------------
// sA[b*128+j] = sum_i A[b,i,j].  grid=16, block=128. Coalesced along j.
// ---------------------------------------------------------------------------
__global__ void k_sums(const float* __restrict__ A) {
    int b = blockIdx.x, j = threadIdx.x;
    const float* Ab = A + (size_t)b * MM * MM;
    float s = 0.f;
#pragma unroll 8
    for (int i = 0; i < MM; i++) s += Ab[i * MM + j];
    g_sA[b * MM + j] = s;
}

// ---------------------------------------------------------------------------
// aggE[r,e] = sum_i A[b,i,j]*E[b,i,j,e].  Streams 128MB of E once.
// 256 threads: 8 warp-groups each own i = grp (mod 8), float4 over e.
// ---------------------------------------------------------------------------
__global__ __launch_bounds__(256) void k_agge(const float* __restrict__ A,
                                              const float* __restrict__ E) {
    int r = blockIdx.x;
    int b = r >> 7, j = r & 127;
    __shared__ float Ac[MM];
    __shared__ float red[8][EH];
    int t = threadIdx.x;
    if (t < MM) Ac[t] = A[(b * MM + t) * MM + j];
    __syncthreads();

    int lane = t & 31, grp = t >> 5;
    const float* Eb = E + ((size_t)b * MM * MM + j) * EH;   // + i*MM*EH + e
    float4 acc = {0.f, 0.f, 0.f, 0.f};
#pragma unroll
    for (int ii = 0; ii < MM; ii += 16) {
        int i0 = ii + grp, i1 = ii + 8 + grp;
        float4 v0 = *(const float4*)(Eb + (size_t)i0 * MM * EH + lane * 4);
        float4 v1 = *(const float4*)(Eb + (size_t)i1 * MM * EH + lane * 4);
        float a0 = Ac[i0], a1 = Ac[i1];
        acc.x += a0 * v0.x + a1 * v1.x;
        acc.y += a0 * v0.y + a1 * v1.y;
        acc.z += a0 * v0.z + a1 * v1.z;
        acc.w += a0 * v0.w + a1 * v1.w;
    }
    *(float4*)&red[grp][lane * 4] = acc;
    __syncthreads();
    if (t < EH) {
        float s = 0.f;
#pragma unroll
        for (int g = 0; g < 8; g++) s += red[g][t];
        g_aggE[(size_t)r * EH + t] = s;
    }
}

// ---------------------------------------------------------------------------
// gemm_atx: AtX[b*128+j, d] = sum_i A[b,i,j] * X[b,i,d]   (A^T @ X per batch)
// BM=32(j) x BN=64(d), K=128(i). Double-buffered, 128 thr, 4x4 micro.
// grid = (2048/32, 256/64) = (64,4)
// ---------------------------------------------------------------------------
__global__ __launch_bounds__(128) void gemm_atx(const float* __restrict__ A,
                                                const float* __restrict__ X) {
    __shared__ float As[2][16][32];
    __shared__ float Bs[2][16][64];
    int tid = threadIdx.x;
    int rowBase = blockIdx.x * 32, colBase = blockIdx.y * 64;
    int b = rowBase >> 7, jloc = rowBase & 127;
    const float* Ab = A + (size_t)b * MM * MM;
    const float* Xb = X + (size_t)b * MM * NH;

    int akk = tid >> 3, ajc = (tid & 7) << 2;     // A tile: k-row, j-col4
    int brow = tid >> 4, bcol = (tid & 15) << 2;  // B tile
    int tx = tid & 15, ty = tid >> 4;

    float acc[4][4] = {};
    const int NT = MM / 16;  // 8

    float4 pa  = *(const float4*)&Ab[(size_t)akk * MM + jloc + ajc];
    float4 pb0 = *(const float4*)&Xb[(size_t)brow * NH + colBase + bcol];
    float4 pb1 = *(const float4*)&Xb[(size_t)(brow + 8) * NH + colBase + bcol];
    *(float4*)&As[0][akk][ajc]      = pa;
    *(float4*)&Bs[0][brow][bcol]     = pb0;
    *(float4*)&Bs[0][brow + 8][bcol] = pb1;
    __syncthreads();

    for (int t = 0; t < NT; t++) {
        int cur = t & 1;
        if (t + 1 < NT) {
            int k0 = (t + 1) * 16;
            pa  = *(const float4*)&Ab[(size_t)(k0 + akk) * MM + jloc + ajc];
            pb0 = *(const float4*)&Xb[(size_t)(k0 + brow) * NH + colBase + bcol];
            pb1 = *(const float4*)&Xb[(size_t)(k0 + brow + 8) * NH + colBase + bcol];
        }
#pragma unroll
        for (int kk = 0; kk < 16; kk++) {
            float4 a4 = *(const float4*)&As[cur][kk][ty * 4];
            float4 b4 = *(const float4*)&Bs[cur][kk][tx * 4];
            float am[4] = {a4.x, a4.y, a4.z, a4.w};
            float bn[4] = {b4.x, b4.y, b4.z, b4.w};
#pragma unroll
            for (int i = 0; i < 4; i++)
#pragma unroll
                for (int jj = 0; jj < 4; jj++)
                    acc[i][jj] += am[i] * bn[jj];
        }
        if (t + 1 < NT) {
            int nxt = cur ^ 1;
            *(float4*)&As[nxt][akk][ajc]      = pa;
            *(float4*)&Bs[nxt][brow][bcol]     = pb0;
            *(float4*)&Bs[nxt][brow + 8][bcol] = pb1;
        }
        __syncthreads();
    }
#pragma unroll
    for (int i = 0; i < 4; i++) {
        int r = rowBase + ty * 4 + i;
#pragma unroll
        for (int jj = 0; jj < 4; jj++)
            g_AtX[(size_t)r * NH + colBase + tx * 4 + jj] = acc[i][jj];
    }
}

// ---------------------------------------------------------------------------
// gemm_h: g_h[r, colOff+n] = relu( sum_k Am[r,k]*W[k,n] + sA[r]*bias[n] )
// BM=32 x BN=64, K=KD (templated: 256 or 128). Double-buffered.
// ---------------------------------------------------------------------------
template <int KD>
__global__ __launch_bounds__(128) void gemm_h(const float* __restrict__ Am,
                                              const float* __restrict__ W,
                                              const float* __restrict__ bias,
                                              int colOff) {
    __shared__ float As[2][16][32];
    __shared__ float Bs[2][16][64];
    int tid = threadIdx.x;
    int rowBase = blockIdx.x * 32, colBase = blockIdx.y * 64;
    constexpr int ldb = KD == 256 ? 256 : 128;  // W is [KD x KD] here (Wv:256x256, We:128x128)

    int arow = tid >> 2, acol = (tid & 3) << 2;
    int brow = tid >> 4, bcol = (tid & 15) << 2;
    int tx = tid & 15, ty = tid >> 4;

    float acc[4][4] = {};
    const int NT = KD / 16;

    float4 pa  = *(const float4*)&Am[(size_t)(rowBase + arow) * KD + acol];
    float4 pb0 = *(const float4*)&W[(size_t)brow * ldb + colBase + bcol];
    float4 pb1 = *(const float4*)&W[(size_t)(brow + 8) * ldb + colBase + bcol];
    As[0][acol + 0][arow] = pa.x;
    As[0][acol + 1][arow] = pa.y;
    As[0][acol + 2][arow] = pa.z;
    As[0][acol + 3][arow] = pa.w;
    *(float4*)&Bs[0][brow][bcol]     = pb0;
    *(float4*)&Bs[0][brow + 8][bcol] = pb1;
    __syncthreads();

    for (int t = 0; t < NT; t++) {
        int cur = t & 1;
        if (t + 1 < NT) {
            int k0 = (t + 1) * 16;
            pa  = *(const float4*)&Am[(size_t)(rowBase + arow) * KD + k0 + acol];
            pb0 = *(const float4*)&W[(size_t)(k0 + brow) * ldb + colBase + bcol];
            pb1 = *(const float4*)&W[(size_t)(k0 + brow + 8) * ldb + colBase + bcol];
        }
#pragma unroll
        for (int kk = 0; kk < 16; kk++) {
            float4 a4 = *(const float4*)&As[cur][kk][ty * 4];
            float4 b4 = *(const float4*)&Bs[cur][kk][tx * 4];
            float am[4] = {a4.x, a4.y, a4.z, a4.w};
            float bn[4] = {b4.x, b4.y, b4.z, b4.w};
#pragma unroll
            for (int i = 0; i < 4; i++)
#pragma unroll
                for (int jj = 0; jj < 4; jj++)
                    acc[i][jj] += am[i] * bn[jj];
        }
        if (t + 1 < NT) {
            int nxt = cur ^ 1;
            As[nxt][acol + 0][arow] = pa.x;
            As[nxt][acol + 1][arow] = pa.y;
            As[nxt][acol + 2][arow] = pa.z;
            As[nxt][acol + 3][arow] = pa.w;
            *(float4*)&Bs[nxt][brow][bcol]     = pb0;
            *(float4*)&Bs[nxt][brow + 8][bcol] = pb1;
        }
        __syncthreads();
    }
#pragma unroll
    for (int i = 0; i < 4; i++) {
        int r = rowBase + ty * 4 + i;
        float sa = g_sA[r];
#pragma unroll
        for (int jj = 0; jj < 4; jj++) {
            int n = colBase + tx * 4 + jj;
            g_h[(size_t)r * HW + colOff + n] = fmaxf(acc[i][jj] + sa * bias[n], 0.f);
        }
    }
}

// ---------------------------------------------------------------------------
// gemm_out: out[r,n] = ( sum_{k<384} h[r,k]*Wu[k,n]
//                      + sum_{k>=384} relu(X[r,k-384])*Wu[k,n] + Wu_b[n] ) * w[r]
// K=640 (40 tiles; boundary 384 is tile-aligned).
// ---------------------------------------------------------------------------
__global__ __launch_bounds__(128) void gemm_out(const float* __restrict__ X,
                                                const float* __restrict__ Wu,
                                                const float* __restrict__ Wub,
                                                const float* __restrict__ w,
                                                float* __restrict__ out) {
    __shared__ float As[2][16][32];
    __shared__ float Bs[2][16][64];
    int tid = threadIdx.x;
    int rowBase = blockIdx.x * 32, colBase = blockIdx.y * 64;

    int arow = tid >> 2, acol = (tid & 3) << 2;
    int brow = tid >> 4, bcol = (tid & 15) << 2;
    int tx = tid & 15, ty = tid >> 4;

    float acc[4][4] = {};
    const int NT = 640 / 16;  // 40

    float4 pa  = *(const float4*)&g_h[(size_t)(rowBase + arow) * HW + acol];
    float4 pb0 = *(const float4*)&Wu[(size_t)brow * NH + colBase + bcol];
    float4 pb1 = *(const float4*)&Wu[(size_t)(brow + 8) * NH + colBase + bcol];
    As[0][acol + 0][arow] = pa.x;
    As[0][acol + 1][arow] = pa.y;
    As[0][acol + 2][arow] = pa.z;
    As[0][acol + 3][arow] = pa.w;
    *(float4*)&Bs[0][brow][bcol]     = pb0;
    *(float4*)&Bs[0][brow + 8][bcol] = pb1;
    __syncthreads();

    for (int t = 0; t < NT; t++) {
        int cur = t & 1;
        if (t + 1 < NT) {
            int k0 = (t + 1) * 16;
            if (k0 < HW) {
                pa = *(const float4*)&g_h[(size_t)(rowBase + arow) * HW + k0 + acol];
            } else {
                pa = *(const float4*)&X[(size_t)(rowBase + arow) * NH + (k0 - HW) + acol];
                pa.x = fmaxf(pa.x, 0.f);
                pa.y = fmaxf(pa.y, 0.f);
                pa.z = fmaxf(pa.z, 0.f);
                pa.w = fmaxf(pa.w, 0.f);
            }
            pb0 = *(const float4*)&Wu[(size_t)(k0 + brow) * NH + colBase + bcol];
            pb1 = *(const float4*)&Wu[(size_t)(k0 + brow + 8) * NH + colBase + bcol];
        }
#pragma unroll
        for (int kk = 0; kk < 16; kk++) {
            float4 a4 = *(const float4*)&As[cur][kk][ty * 4];
            float4 b4 = *(const float4*)&Bs[cur][kk][tx * 4];
            float am[4] = {a4.x, a4.y, a4.z, a4.w};
            float bn[4] = {b4.x, b4.y, b4.z, b4.w};
#pragma unroll
            for (int i = 0; i < 4; i++)
#pragma unroll
                for (int jj = 0; jj < 4; jj++)
                    acc[i][jj] += am[i] * bn[jj];
        }
        if (t + 1 < NT) {
            int nxt = cur ^ 1;
            As[nxt][acol + 0][arow] = pa.x;
            As[nxt][acol + 1][arow] = pa.y;
            As[nxt][acol + 2][arow] = pa.z;
            As[nxt][acol + 3][arow] = pa.w;
            *(float4*)&Bs[nxt][brow][bcol]     = pb0;
            *(float4*)&Bs[nxt][brow + 8][bcol] = pb1;
        }
        __syncthreads();
    }
#pragma unroll
    for (int i = 0; i < 4; i++) {
        int r = rowBase + ty * 4 + i;
        float wr = w[r];
#pragma unroll
        for (int jj = 0; jj < 4; jj++) {
            int n = colBase + tx * 4 + jj;
            out[(size_t)r * NH + n] = (acc[i][jj] + Wub[n]) * wr;
        }
    }
}

// ---------------------------------------------------------------------------
extern "C" void kernel_launch(void* const* d_in, const int* in_sizes, int n_in,
                              void* d_out, int out_size) {
    const float* X    = (const float*)d_in[0];
    const float* E    = (const float*)d_in[1];
    const float* A    = (const float*)d_in[2];
    const float* w    = (const float*)d_in[3];
    const float* Wv_w = (const float*)d_in[4];
    const float* Wv_b = (const float*)d_in[5];
    const float* We_w = (const float*)d_in[6];
    const float* We_b = (const float*)d_in[7];
    const float* Wu_w = (const float*)d_in[8];
    const float* Wu_b = (const float*)d_in[9];
    float* out = (float*)d_out;

    float *p_AtX, *p_aggE;
    cudaGetSymbolAddress((void**)&p_AtX,  g_AtX);
    cudaGetSymbolAddress((void**)&p_aggE, g_aggE);

    // Fork a side stream for the E-stream + edge GEMM (independent of node chain)
    cudaStream_t sB;
    cudaStreamCreateWithFlags(&sB, cudaStreamNonBlocking);
    cudaEvent_t e0, eS, eB;
    cudaEventCreateWithFlags(&e0, cudaEventDisableTiming);
    cudaEventCreateWithFlags(&eS, cudaEventDisableTiming);
    cudaEventCreateWithFlags(&eB, cudaEventDisableTiming);

    cudaEventRecord(e0, 0);
    cudaStreamWaitEvent(sB, e0, 0);

    // Stream B: the DRAM-bound E reduction
    k_agge<<<RR, 256, 0, sB>>>(A, E);

    // Stream 0: node chain
    k_sums<<<BB, MM>>>(A);
    cudaEventRecord(eS, 0);                           // sA ready
    gemm_atx<<<dim3(RR / 32, NH / 64), 128>>>(A, X);
    gemm_h<256><<<dim3(RR / 32, NH / 64), 128>>>(p_AtX, Wv_w, Wv_b, 0);

    // Stream B: edge GEMM (needs aggE on sB + sA from stream 0)
    cudaStreamWaitEvent(sB, eS, 0);
    gemm_h<128><<<dim3(RR / 32, EH / 64), 128, 0, sB>>>(p_aggE, We_w, We_b, NH);
    cudaEventRecord(eB, sB);

    // Join, final GEMM
    cudaStreamWaitEvent(0, eB, 0);
    gemm_out<<<dim3(RR / 32, NH / 64), 128>>>(X, Wu_w, Wu_b, w, out);

    cudaEventDestroy(e0);
    cudaEventDestroy(eS);
    cudaEventDestroy(eB);
    cudaStreamDestroy(sB);
}

// round 3
// speedup vs baseline: 1.6474x; 1.0272x over previous
#include <cuda_runtime.h>

#define BB 16
#define MM 128
#define NH 256
#define EH 128
#define RR (BB*MM)          // 2048

// L2-resident scratch
__device__ float g_AtX[RR * NH];        // A^T @ X
__device__ float g_sA [RR];
__device__ float g_aggE[RR * EH];
__device__ float g_hN [RR * NH];        // relu(node branch)
__device__ float g_hE [RR * EH];        // relu(edge branch)
__device__ float g_pN [2][RR * NH];     // partials for AtX @ Wv
__device__ float g_pO [5][RR * NH];     // partials for final GEMM

// ---------------------------------------------------------------------------
// sA[b*128+j] = sum_i A[b,i,j]
// ---------------------------------------------------------------------------
__global__ void k_sums(const float* __restrict__ A) {
    int b = blockIdx.x, j = threadIdx.x;
    const float* Ab = A + (size_t)b * MM * MM;
    float s = 0.f;
#pragma unroll 8
    for (int i = 0; i < MM; i++) s += Ab[i * MM + j];
    g_sA[b * MM + j] = s;
}

// ---------------------------------------------------------------------------
// aggE[r,e] = sum_i A[b,i,j]*E[b,i,j,e].  DRAM-bound: streams 128MB of E once.
// ---------------------------------------------------------------------------
__global__ __launch_bounds__(256) void k_agge(const float* __restrict__ A,
                                              const float* __restrict__ E) {
    int r = blockIdx.x;
    int b = r >> 7, j = r & 127;
    __shared__ float Ac[MM];
    __shared__ float red[8][EH];
    int t = threadIdx.x;
    if (t < MM) Ac[t] = A[(b * MM + t) * MM + j];
    __syncthreads();

    int lane = t & 31, grp = t >> 5;
    const float* Eb = E + ((size_t)b * MM * MM + j) * EH;
    float4 acc = {0.f, 0.f, 0.f, 0.f};
#pragma unroll
    for (int ii = 0; ii < MM; ii += 16) {
        int i0 = ii + grp, i1 = ii + 8 + grp;
        float4 v0 = *(const float4*)(Eb + (size_t)i0 * MM * EH + lane * 4);
        float4 v1 = *(const float4*)(Eb + (size_t)i1 * MM * EH + lane * 4);
        float a0 = Ac[i0], a1 = Ac[i1];
        acc.x += a0 * v0.x + a1 * v1.x;
        acc.y += a0 * v0.y + a1 * v1.y;
        acc.z += a0 * v0.z + a1 * v1.z;
        acc.w += a0 * v0.w + a1 * v1.w;
    }
    *(float4*)&red[grp][lane * 4] = acc;
    __syncthreads();
    if (t < EH) {
        float s = 0.f;
#pragma unroll
        for (int g = 0; g < 8; g++) s += red[g][t];
        g_aggE[(size_t)r * EH + t] = s;
    }
}

// ---------------------------------------------------------------------------
// gemm_atx: AtX[b*128+j, d] = sum_i A[b,i,j] * X[b,i,d]
// ---------------------------------------------------------------------------
__global__ __launch_bounds__(128) void gemm_atx(const float* __restrict__ A,
                                                const float* __restrict__ X) {
    __shared__ float As[2][16][32];
    __shared__ float Bs[2][16][64];
    int tid = threadIdx.x;
    int rowBase = blockIdx.x * 32, colBase = blockIdx.y * 64;
    int b = rowBase >> 7, jloc = rowBase & 127;
    const float* Ab = A + (size_t)b * MM * MM;
    const float* Xb = X + (size_t)b * MM * NH;

    int akk = tid >> 3, ajc = (tid & 7) << 2;
    int brow = tid >> 4, bcol = (tid & 15) << 2;
    int tx = tid & 15, ty = tid >> 4;

    float acc[4][4] = {};
    const int NT = MM / 16;

    float4 pa  = *(const float4*)&Ab[(size_t)akk * MM + jloc + ajc];
    float4 pb0 = *(const float4*)&Xb[(size_t)brow * NH + colBase + bcol];
    float4 pb1 = *(const float4*)&Xb[(size_t)(brow + 8) * NH + colBase + bcol];
    *(float4*)&As[0][akk][ajc]       = pa;
    *(float4*)&Bs[0][brow][bcol]     = pb0;
    *(float4*)&Bs[0][brow + 8][bcol] = pb1;
    __syncthreads();

    for (int t = 0; t < NT; t++) {
        int cur = t & 1;
        if (t + 1 < NT) {
            int k0 = (t + 1) * 16;
            pa  = *(const float4*)&Ab[(size_t)(k0 + akk) * MM + jloc + ajc];
            pb0 = *(const float4*)&Xb[(size_t)(k0 + brow) * NH + colBase + bcol];
            pb1 = *(const float4*)&Xb[(size_t)(k0 + brow + 8) * NH + colBase + bcol];
        }
#pragma unroll
        for (int kk = 0; kk < 16; kk++) {
            float4 a4 = *(const float4*)&As[cur][kk][ty * 4];
            float4 b4 = *(const float4*)&Bs[cur][kk][tx * 4];
            float am[4] = {a4.x, a4.y, a4.z, a4.w};
            float bn[4] = {b4.x, b4.y, b4.z, b4.w};
#pragma unroll
            for (int i = 0; i < 4; i++)
#pragma unroll
                for (int jj = 0; jj < 4; jj++)
                    acc[i][jj] += am[i] * bn[jj];
        }
        if (t + 1 < NT) {
            int nxt = cur ^ 1;
            *(float4*)&As[nxt][akk][ajc]       = pa;
            *(float4*)&Bs[nxt][brow][bcol]     = pb0;
            *(float4*)&Bs[nxt][brow + 8][bcol] = pb1;
        }
        __syncthreads();
    }
#pragma unroll
    for (int i = 0; i < 4; i++) {
        int r = rowBase + ty * 4 + i;
#pragma unroll
        for (int jj = 0; jj < 4; jj++)
            g_AtX[(size_t)r * NH + colBase + tx * 4 + jj] = acc[i][jj];
    }
}

// ---------------------------------------------------------------------------
// gemm_p: K=128-chunk partial GEMM.
//   P[r*256 + colBase+n] = sum_{k<128} a(Am[r*lda + kaOff+k]) * B[(kbOff+k)*ldb + colBase+n]
//   a() = relu if RELU (used for the X branch).
// BM=32, BN=64, BK=16, 128 threads, double-buffered. grid=(64, Ndim/64)
// ---------------------------------------------------------------------------
template <bool RELU>
__global__ __launch_bounds__(128) void gemm_p(const float* __restrict__ Am, int lda, int kaOff,
                                              const float* __restrict__ B,  int ldb, int kbOff,
                                              float* __restrict__ P) {
    __shared__ float As[2][16][32];
    __shared__ float Bs[2][16][64];
    int tid = threadIdx.x;
    int rowBase = blockIdx.x * 32, colBase = blockIdx.y * 64;

    int arow = tid >> 2, acol = (tid & 3) << 2;
    int brow = tid >> 4, bcol = (tid & 15) << 2;
    int tx = tid & 15, ty = tid >> 4;

    float acc[4][4] = {};
    const int NT = 8;   // K = 128

    const float* Abase = Am + (size_t)(rowBase + arow) * lda + kaOff;
    const float* Bbase = B + (size_t)kbOff * ldb + colBase;

    float4 pa  = *(const float4*)&Abase[acol];
    float4 pb0 = *(const float4*)&Bbase[(size_t)brow * ldb + bcol];
    float4 pb1 = *(const float4*)&Bbase[(size_t)(brow + 8) * ldb + bcol];
    if (RELU) {
        pa.x = fmaxf(pa.x, 0.f); pa.y = fmaxf(pa.y, 0.f);
        pa.z = fmaxf(pa.z, 0.f); pa.w = fmaxf(pa.w, 0.f);
    }
    As[0][acol + 0][arow] = pa.x;
    As[0][acol + 1][arow] = pa.y;
    As[0][acol + 2][arow] = pa.z;
    As[0][acol + 3][arow] = pa.w;
    *(float4*)&Bs[0][brow][bcol]     = pb0;
    *(float4*)&Bs[0][brow + 8][bcol] = pb1;
    __syncthreads();

    for (int t = 0; t < NT; t++) {
        int cur = t & 1;
        if (t + 1 < NT) {
            int k0 = (t + 1) * 16;
            pa  = *(const float4*)&Abase[k0 + acol];
            pb0 = *(const float4*)&Bbase[(size_t)(k0 + brow) * ldb + bcol];
            pb1 = *(const float4*)&Bbase[(size_t)(k0 + brow + 8) * ldb + bcol];
            if (RELU) {
                pa.x = fmaxf(pa.x, 0.f); pa.y = fmaxf(pa.y, 0.f);
                pa.z = fmaxf(pa.z, 0.f); pa.w = fmaxf(pa.w, 0.f);
            }
        }
#pragma unroll
        for (int kk = 0; kk < 16; kk++) {
            float4 a4 = *(const float4*)&As[cur][kk][ty * 4];
            float4 b4 = *(const float4*)&Bs[cur][kk][tx * 4];
            float am[4] = {a4.x, a4.y, a4.z, a4.w};
            float bn[4] = {b4.x, b4.y, b4.z, b4.w};
#pragma unroll
            for (int i = 0; i < 4; i++)
#pragma unroll
                for (int jj = 0; jj < 4; jj++)
                    acc[i][jj] += am[i] * bn[jj];
        }
        if (t + 1 < NT) {
            int nxt = cur ^ 1;
            As[nxt][acol + 0][arow] = pa.x;
            As[nxt][acol + 1][arow] = pa.y;
            As[nxt][acol + 2][arow] = pa.z;
            As[nxt][acol + 3][arow] = pa.w;
            *(float4*)&Bs[nxt][brow][bcol]     = pb0;
            *(float4*)&Bs[nxt][brow + 8][bcol] = pb1;
        }
        __syncthreads();
    }
#pragma unroll
    for (int i = 0; i < 4; i++) {
        int r = rowBase + ty * 4 + i;
#pragma unroll
        for (int jj = 0; jj < 4; jj++)
            P[(size_t)r * NH + colBase + tx * 4 + jj] = acc[i][jj];
    }
}

// ---------------------------------------------------------------------------
// gemm_hE: g_hE[r,n] = relu( sum_{k<128} aggE[r,k]*We[k,n] + sA[r]*We_b[n] )
// ---------------------------------------------------------------------------
__global__ __launch_bounds__(128) void gemm_hE(const float* __restrict__ We,
                                               const float* __restrict__ Web) {
    __shared__ float As[2][16][32];
    __shared__ float Bs[2][16][64];
    int tid = threadIdx.x;
    int rowBase = blockIdx.x * 32, colBase = blockIdx.y * 64;

    int arow = tid >> 2, acol = (tid & 3) << 2;
    int brow = tid >> 4, bcol = (tid & 15) << 2;
    int tx = tid & 15, ty = tid >> 4;

    float acc[4][4] = {};
    const int NT = 8;

    const float* Abase = g_aggE + (size_t)(rowBase + arow) * EH;

    float4 pa  = *(const float4*)&Abase[acol];
    float4 pb0 = *(const float4*)&We[(size_t)brow * EH + colBase + bcol];
    float4 pb1 = *(const float4*)&We[(size_t)(brow + 8) * EH + colBase + bcol];
    As[0][acol + 0][arow] = pa.x;
    As[0][acol + 1][arow] = pa.y;
    As[0][acol + 2][arow] = pa.z;
    As[0][acol + 3][arow] = pa.w;
    *(float4*)&Bs[0][brow][bcol]     = pb0;
    *(float4*)&Bs[0][brow + 8][bcol] = pb1;
    __syncthreads();

    for (int t = 0; t < NT; t++) {
        int cur = t & 1;
        if (t + 1 < NT) {
            int k0 = (t + 1) * 16;
            pa  = *(const float4*)&Abase[k0 + acol];
            pb0 = *(const float4*)&We[(size_t)(k0 + brow) * EH + colBase + bcol];
            pb1 = *(const float4*)&We[(size_t)(k0 + brow + 8) * EH + colBase + bcol];
        }
#pragma unroll
        for (int kk = 0; kk < 16; kk++) {
            float4 a4 = *(const float4*)&As[cur][kk][ty * 4];
            float4 b4 = *(const float4*)&Bs[cur][kk][tx * 4];
            float am[4] = {a4.x, a4.y, a4.z, a4.w};
            float bn[4] = {b4.x, b4.y, b4.z, b4.w};
#pragma unroll
            for (int i = 0; i < 4; i++)
#pragma unroll
                for (int jj = 0; jj < 4; jj++)
                    acc[i][jj] += am[i] * bn[jj];
        }
        if (t + 1 < NT) {
            int nxt = cur ^ 1;
            As[nxt][acol + 0][arow] = pa.x;
            As[nxt][acol + 1][arow] = pa.y;
            As[nxt][acol + 2][arow] = pa.z;
            As[nxt][acol + 3][arow] = pa.w;
            *(float4*)&Bs[nxt][brow][bcol]     = pb0;
            *(float4*)&Bs[nxt][brow + 8][bcol] = pb1;
        }
        __syncthreads();
    }
#pragma unroll
    for (int i = 0; i < 4; i++) {
        int r = rowBase + ty * 4 + i;
        float sa = g_sA[r];
#pragma unroll
        for (int jj = 0; jj < 4; jj++) {
            int n = colBase + tx * 4 + jj;
            g_hE[(size_t)r * EH + n] = fmaxf(acc[i][jj] + sa * Web[n], 0.f);
        }
    }
}

// ---------------------------------------------------------------------------
// k_reluN: g_hN = relu(pN0 + pN1 + sA*Wv_b).  grid=2048, block=256.
// ---------------------------------------------------------------------------
__global__ void k_reluN(const float* __restrict__ Wvb) {
    int r = blockIdx.x, n = threadIdx.x;
    size_t idx = (size_t)r * NH + n;
    g_hN[idx] = fmaxf(g_pN[0][idx] + g_pN[1][idx] + g_sA[r] * Wvb[n], 0.f);
}

// ---------------------------------------------------------------------------
// k_final: out = (pO0+..+pO4 + Wu_b) * w
// ---------------------------------------------------------------------------
__global__ void k_final(const float* __restrict__ Wub, const float* __restrict__ w,
                        float* __restrict__ out) {
    int r = blockIdx.x, n = threadIdx.x;
    size_t idx = (size_t)r * NH + n;
    float s = g_pO[0][idx] + g_pO[1][idx] + g_pO[2][idx] + g_pO[3][idx] + g_pO[4][idx];
    out[idx] = (s + Wub[n]) * w[r];
}

// ---------------------------------------------------------------------------
extern "C" void kernel_launch(void* const* d_in, const int* in_sizes, int n_in,
                              void* d_out, int out_size) {
    const float* X    = (const float*)d_in[0];
    const float* E    = (const float*)d_in[1];
    const float* A    = (const float*)d_in[2];
    const float* w    = (const float*)d_in[3];
    const float* Wv_w = (const float*)d_in[4];
    const float* Wv_b = (const float*)d_in[5];
    const float* We_w = (const float*)d_in[6];
    const float* We_b = (const float*)d_in[7];
    const float* Wu_w = (const float*)d_in[8];
    const float* Wu_b = (const float*)d_in[9];
    float* out = (float*)d_out;

    float *p_AtX, *p_hN, *p_hE, *p_pN, *p_pO;
    cudaGetSymbolAddress((void**)&p_AtX, g_AtX);
    cudaGetSymbolAddress((void**)&p_hN,  g_hN);
    cudaGetSymbolAddress((void**)&p_hE,  g_hE);
    cudaGetSymbolAddress((void**)&p_pN,  g_pN);
    cudaGetSymbolAddress((void**)&p_pO,  g_pO);
    float* pN0 = p_pN;
    float* pN1 = p_pN + (size_t)RR * NH;
    float* pO0 = p_pO;
    float* pO1 = p_pO + 1 * (size_t)RR * NH;
    float* pO2 = p_pO + 2 * (size_t)RR * NH;
    float* pO3 = p_pO + 3 * (size_t)RR * NH;
    float* pO4 = p_pO + 4 * (size_t)RR * NH;

    cudaStream_t sB, sC, sD;
    cudaStreamCreateWithFlags(&sB, cudaStreamNonBlocking);
    cudaStreamCreateWithFlags(&sC, cudaStreamNonBlocking);
    cudaStreamCreateWithFlags(&sD, cudaStreamNonBlocking);
    cudaEvent_t e0, eS, eX, eN, eD1, eD2, eB, eC;
    cudaEventCreateWithFlags(&e0,  cudaEventDisableTiming);
    cudaEventCreateWithFlags(&eS,  cudaEventDisableTiming);
    cudaEventCreateWithFlags(&eX,  cudaEventDisableTiming);
    cudaEventCreateWithFlags(&eN,  cudaEventDisableTiming);
    cudaEventCreateWithFlags(&eD1, cudaEventDisableTiming);
    cudaEventCreateWithFlags(&eD2, cudaEventDisableTiming);
    cudaEventCreateWithFlags(&eB,  cudaEventDisableTiming);
    cudaEventCreateWithFlags(&eC,  cudaEventDisableTiming);

    dim3 gP(RR / 32, NH / 64);   // (64,4)
    dim3 gE(RR / 32, EH / 64);   // (64,2)

    cudaEventRecord(e0, 0);
    cudaStreamWaitEvent(sB, e0, 0);
    cudaStreamWaitEvent(sC, e0, 0);
    cudaStreamWaitEvent(sD, e0, 0);

    // sB: DRAM-bound E reduction chain
    k_agge<<<RR, 256, 0, sB>>>(A, E);

    // sC: input-independent X branch of the final GEMM (relu(X) @ Wu[384:640])
    gemm_p<true><<<gP, 128, 0, sC>>>(X, NH, 0,   Wu_w, NH, 384, pO0);
    gemm_p<true><<<gP, 128, 0, sC>>>(X, NH, 128, Wu_w, NH, 512, pO1);
    cudaEventRecord(eC, sC);

    // s0: node chain
    k_sums<<<BB, MM>>>(A);
    cudaEventRecord(eS, 0);
    gemm_atx<<<dim3(RR / 32, NH / 64), 128>>>(A, X);
    cudaEventRecord(eX, 0);

    // split AtX @ Wv across s0 / sD
    cudaStreamWaitEvent(sD, eX, 0);
    gemm_p<false><<<gP, 128, 0, sD>>>(p_AtX, NH, 128, Wv_w, NH, 128, pN1);
    cudaEventRecord(eD1, sD);
    gemm_p<false><<<gP, 128>>>(p_AtX, NH, 0, Wv_w, NH, 0, pN0);
    cudaStreamWaitEvent(0, eD1, 0);
    k_reluN<<<RR, NH>>>(Wv_b);
    cudaEventRecord(eN, 0);

    // split hN @ Wu[0:256] across s0 / sD
    cudaStreamWaitEvent(sD, eN, 0);
    gemm_p<false><<<gP, 128, 0, sD>>>(p_hN, NH, 128, Wu_w, NH, 128, pO3);
    cudaEventRecord(eD2, sD);
    gemm_p<false><<<gP, 128>>>(p_hN, NH, 0, Wu_w, NH, 0, pO2);

    // sB: edge chain (needs sA)
    cudaStreamWaitEvent(sB, eS, 0);
    gemm_hE<<<gE, 128, 0, sB>>>(We_w, We_b);
    gemm_p<false><<<gP, 128, 0, sB>>>(p_hE, EH, 0, Wu_w, NH, 256, pO4);
    cudaEventRecord(eB, sB);

    // join + final epilogue
    cudaStreamWaitEvent(0, eB, 0);
    cudaStreamWaitEvent(0, eC, 0);
    cudaStreamWaitEvent(0, eD2, 0);
    k_final<<<RR, NH>>>(Wu_b, w, out);

    cudaEventDestroy(e0);  cudaEventDestroy(eS);  cudaEventDestroy(eX);
    cudaEventDestroy(eN);  cudaEventDestroy(eD1); cudaEventDestroy(eD2);
    cudaEventDestroy(eB);  cudaEventDestroy(eC);
    cudaStreamDestroy(sB); cudaStreamDestroy(sC); cudaStreamDestroy(sD);
}

// round 4
// speedup vs baseline: 1.6819x; 1.0209x over previous
#include <cuda_runtime.h>

#define BB 16
#define MM 128
#define NH 256
#define EH 128
#define RR (BB*MM)          // 2048

// L2-resident scratch
__device__ float g_AtX[RR * NH];
__device__ float g_sA [RR];
__device__ float g_aggE[RR * EH];
__device__ float g_hN [RR * NH];
__device__ float g_hE [RR * EH];
__device__ float g_pN [2][RR * NH];
__device__ float g_pO [5][RR * NH];

// ---------------------------------------------------------------------------
// aggE[r,e] = sum_i A[b,i,j]*E[b,i,j,e].  DRAM-bound: streams 128MB of E once.
// ---------------------------------------------------------------------------
__global__ __launch_bounds__(256) void k_agge(const float* __restrict__ A,
                                              const float* __restrict__ E) {
    int r = blockIdx.x;
    int b = r >> 7, j = r & 127;
    __shared__ float Ac[MM];
    __shared__ float red[8][EH];
    int t = threadIdx.x;
    if (t < MM) Ac[t] = A[(b * MM + t) * MM + j];
    __syncthreads();

    int lane = t & 31, grp = t >> 5;
    const float* Eb = E + ((size_t)b * MM * MM + j) * EH;
    float4 acc = {0.f, 0.f, 0.f, 0.f};
#pragma unroll
    for (int ii = 0; ii < MM; ii += 16) {
        int i0 = ii + grp, i1 = ii + 8 + grp;
        float4 v0 = *(const float4*)(Eb + (size_t)i0 * MM * EH + lane * 4);
        float4 v1 = *(const float4*)(Eb + (size_t)i1 * MM * EH + lane * 4);
        float a0 = Ac[i0], a1 = Ac[i1];
        acc.x += a0 * v0.x + a1 * v1.x;
        acc.y += a0 * v0.y + a1 * v1.y;
        acc.z += a0 * v0.z + a1 * v1.z;
        acc.w += a0 * v0.w + a1 * v1.w;
    }
    *(float4*)&red[grp][lane * 4] = acc;
    __syncthreads();
    if (t < EH) {
        float s = 0.f;
#pragma unroll
        for (int g = 0; g < 8; g++) s += red[g][t];
        g_aggE[(size_t)r * EH + t] = s;
    }
}

// ---------------------------------------------------------------------------
// gemm_atx: AtX[b*128+j, d] = sum_i A[b,i,j] * X[b,i,d]
// Also folds sA[r] = sum_i A[b,i,j]  (computed by blockIdx.y==0, tx==0 writes)
// ---------------------------------------------------------------------------
__global__ __launch_bounds__(128) void gemm_atx(const float* __restrict__ A,
                                                const float* __restrict__ X) {
    __shared__ float As[2][16][32];
    __shared__ float Bs[2][16][64];
    int tid = threadIdx.x;
    int rowBase = blockIdx.x * 32, colBase = blockIdx.y * 64;
    int b = rowBase >> 7, jloc = rowBase & 127;
    const float* Ab = A + (size_t)b * MM * MM;
    const float* Xb = X + (size_t)b * MM * NH;

    int akk = tid >> 3, ajc = (tid & 7) << 2;
    int brow = tid >> 4, bcol = (tid & 15) << 2;
    int tx = tid & 15, ty = tid >> 4;

    float acc[4][4] = {};
    float sa[4] = {0.f, 0.f, 0.f, 0.f};
    const int NT = MM / 16;

    float4 pa  = *(const float4*)&Ab[(size_t)akk * MM + jloc + ajc];
    float4 pb0 = *(const float4*)&Xb[(size_t)brow * NH + colBase + bcol];
    float4 pb1 = *(const float4*)&Xb[(size_t)(brow + 8) * NH + colBase + bcol];
    *(float4*)&As[0][akk][ajc]       = pa;
    *(float4*)&Bs[0][brow][bcol]     = pb0;
    *(float4*)&Bs[0][brow + 8][bcol] = pb1;
    __syncthreads();

    for (int t = 0; t < NT; t++) {
        int cur = t & 1;
        if (t + 1 < NT) {
            int k0 = (t + 1) * 16;
            pa  = *(const float4*)&Ab[(size_t)(k0 + akk) * MM + jloc + ajc];
            pb0 = *(const float4*)&Xb[(size_t)(k0 + brow) * NH + colBase + bcol];
            pb1 = *(const float4*)&Xb[(size_t)(k0 + brow + 8) * NH + colBase + bcol];
        }
#pragma unroll
        for (int kk = 0; kk < 16; kk++) {
            float4 a4 = *(const float4*)&As[cur][kk][ty * 4];
            float4 b4 = *(const float4*)&Bs[cur][kk][tx * 4];
            float am[4] = {a4.x, a4.y, a4.z, a4.w};
            float bn[4] = {b4.x, b4.y, b4.z, b4.w};
#pragma unroll
            for (int i = 0; i < 4; i++)
#pragma unroll
                for (int jj = 0; jj < 4; jj++)
                    acc[i][jj] += am[i] * bn[jj];
            sa[0] += am[0]; sa[1] += am[1]; sa[2] += am[2]; sa[3] += am[3];
        }
        if (t + 1 < NT) {
            int nxt = cur ^ 1;
            *(float4*)&As[nxt][akk][ajc]       = pa;
            *(float4*)&Bs[nxt][brow][bcol]     = pb0;
            *(float4*)&Bs[nxt][brow + 8][bcol] = pb1;
        }
        __syncthreads();
    }
#pragma unroll
    for (int i = 0; i < 4; i++) {
        int r = rowBase + ty * 4 + i;
#pragma unroll
        for (int jj = 0; jj < 4; jj++)
            g_AtX[(size_t)r * NH + colBase + tx * 4 + jj] = acc[i][jj];
        if (blockIdx.y == 0 && tx == 0) g_sA[r] = sa[i];
    }
}

// ---------------------------------------------------------------------------
// gemm_p: K=128-chunk partial GEMM, z-split over blockIdx.z.
//   P[z][r, colBase+n] = sum_{k<128} a(Am[r*lda + kaOff + z*128 + k])
//                                   * B[(kbOff + z*128 + k)*ldb + colBase+n]
// BM=32, BN=64, BK=16, 128 threads, double-buffered.
// ---------------------------------------------------------------------------
template <bool RELU>
__global__ __launch_bounds__(128) void gemm_p(const float* __restrict__ Am, int lda, int kaOff,
                                              const float* __restrict__ B,  int ldb, int kbOff,
                                              float* __restrict__ P) {
    __shared__ float As[2][16][32];
    __shared__ float Bs[2][16][64];
    int tid = threadIdx.x;
    int rowBase = blockIdx.x * 32, colBase = blockIdx.y * 64;
    int z = blockIdx.z;
    kaOff += z * 128;
    kbOff += z * 128;
    P += (size_t)z * RR * NH;

    int arow = tid >> 2, acol = (tid & 3) << 2;
    int brow = tid >> 4, bcol = (tid & 15) << 2;
    int tx = tid & 15, ty = tid >> 4;

    float acc[4][4] = {};
    const int NT = 8;

    const float* Abase = Am + (size_t)(rowBase + arow) * lda + kaOff;
    const float* Bbase = B + (size_t)kbOff * ldb + colBase;

    float4 pa  = *(const float4*)&Abase[acol];
    float4 pb0 = *(const float4*)&Bbase[(size_t)brow * ldb + bcol];
    float4 pb1 = *(const float4*)&Bbase[(size_t)(brow + 8) * ldb + bcol];
    if (RELU) {
        pa.x = fmaxf(pa.x, 0.f); pa.y = fmaxf(pa.y, 0.f);
        pa.z = fmaxf(pa.z, 0.f); pa.w = fmaxf(pa.w, 0.f);
    }
    As[0][acol + 0][arow] = pa.x;
    As[0][acol + 1][arow] = pa.y;
    As[0][acol + 2][arow] = pa.z;
    As[0][acol + 3][arow] = pa.w;
    *(float4*)&Bs[0][brow][bcol]     = pb0;
    *(float4*)&Bs[0][brow + 8][bcol] = pb1;
    __syncthreads();

    for (int t = 0; t < NT; t++) {
        int cur = t & 1;
        if (t + 1 < NT) {
            int k0 = (t + 1) * 16;
            pa  = *(const float4*)&Abase[k0 + acol];
            pb0 = *(const float4*)&Bbase[(size_t)(k0 + brow) * ldb + bcol];
            pb1 = *(const float4*)&Bbase[(size_t)(k0 + brow + 8) * ldb + bcol];
            if (RELU) {
                pa.x = fmaxf(pa.x, 0.f); pa.y = fmaxf(pa.y, 0.f);
                pa.z = fmaxf(pa.z, 0.f); pa.w = fmaxf(pa.w, 0.f);
            }
        }
#pragma unroll
        for (int kk = 0; kk < 16; kk++) {
            float4 a4 = *(const float4*)&As[cur][kk][ty * 4];
            float4 b4 = *(const float4*)&Bs[cur][kk][tx * 4];
            float am[4] = {a4.x, a4.y, a4.z, a4.w};
            float bn[4] = {b4.x, b4.y, b4.z, b4.w};
#pragma unroll
            for (int i = 0; i < 4; i++)
#pragma unroll
                for (int jj = 0; jj < 4; jj++)
                    acc[i][jj] += am[i] * bn[jj];
        }
        if (t + 1 < NT) {
            int nxt = cur ^ 1;
            As[nxt][acol + 0][arow] = pa.x;
            As[nxt][acol + 1][arow] = pa.y;
            As[nxt][acol + 2][arow] = pa.z;
            As[nxt][acol + 3][arow] = pa.w;
            *(float4*)&Bs[nxt][brow][bcol]     = pb0;
            *(float4*)&Bs[nxt][brow + 8][bcol] = pb1;
        }
        __syncthreads();
    }
#pragma unroll
    for (int i = 0; i < 4; i++) {
        int r = rowBase + ty * 4 + i;
#pragma unroll
        for (int jj = 0; jj < 4; jj++)
            P[(size_t)r * NH + colBase + tx * 4 + jj] = acc[i][jj];
    }
}

// ---------------------------------------------------------------------------
// gemm_hE: g_hE[r,n] = relu( sum_{k<128} aggE[r,k]*We[k,n] + sA[r]*We_b[n] )
// ---------------------------------------------------------------------------
__global__ __launch_bounds__(128) void gemm_hE(const float* __restrict__ We,
                                               const float* __restrict__ Web) {
    __shared__ float As[2][16][32];
    __shared__ float Bs[2][16][64];
    int tid = threadIdx.x;
    int rowBase = blockIdx.x * 32, colBase = blockIdx.y * 64;

    int arow = tid >> 2, acol = (tid & 3) << 2;
    int brow = tid >> 4, bcol = (tid & 15) << 2;
    int tx = tid & 15, ty = tid >> 4;

    float acc[4][4] = {};
    const int NT = 8;

    const float* Abase = g_aggE + (size_t)(rowBase + arow) * EH;

    float4 pa  = *(const float4*)&Abase[acol];
    float4 pb0 = *(const float4*)&We[(size_t)brow * EH + colBase + bcol];
    float4 pb1 = *(const float4*)&We[(size_t)(brow + 8) * EH + colBase + bcol];
    As[0][acol + 0][arow] = pa.x;
    As[0][acol + 1][arow] = pa.y;
    As[0][acol + 2][arow] = pa.z;
    As[0][acol + 3][arow] = pa.w;
    *(float4*)&Bs[0][brow][bcol]     = pb0;
    *(float4*)&Bs[0][brow + 8][bcol] = pb1;
    __syncthreads();

    for (int t = 0; t < NT; t++) {
        int cur = t & 1;
        if (t + 1 < NT) {
            int k0 = (t + 1) * 16;
            pa  = *(const float4*)&Abase[k0 + acol];
            pb0 = *(const float4*)&We[(size_t)(k0 + brow) * EH + colBase + bcol];
            pb1 = *(const float4*)&We[(size_t)(k0 + brow + 8) * EH + colBase + bcol];
        }
#pragma unroll
        for (int kk = 0; kk < 16; kk++) {
            float4 a4 = *(const float4*)&As[cur][kk][ty * 4];
            float4 b4 = *(const float4*)&Bs[cur][kk][tx * 4];
            float am[4] = {a4.x, a4.y, a4.z, a4.w};
            float bn[4] = {b4.x, b4.y, b4.z, b4.w};
#pragma unroll
            for (int i = 0; i < 4; i++)
#pragma unroll
                for (int jj = 0; jj < 4; jj++)
                    acc[i][jj] += am[i] * bn[jj];
        }
        if (t + 1 < NT) {
            int nxt = cur ^ 1;
            As[nxt][acol + 0][arow] = pa.x;
            As[nxt][acol + 1][arow] = pa.y;
            As[nxt][acol + 2][arow] = pa.z;
            As[nxt][acol + 3][arow] = pa.w;
            *(float4*)&Bs[nxt][brow][bcol]     = pb0;
            *(float4*)&Bs[nxt][brow + 8][bcol] = pb1;
        }
        __syncthreads();
    }
#pragma unroll
    for (int i = 0; i < 4; i++) {
        int r = rowBase + ty * 4 + i;
        float sa = g_sA[r];
#pragma unroll
        for (int jj = 0; jj < 4; jj++) {
            int n = colBase + tx * 4 + jj;
            g_hE[(size_t)r * EH + n] = fmaxf(acc[i][jj] + sa * Web[n], 0.f);
        }
    }
}

// ---------------------------------------------------------------------------
__global__ void k_reluN(const float* __restrict__ Wvb) {
    int r = blockIdx.x, n = threadIdx.x;
    size_t idx = (size_t)r * NH + n;
    g_hN[idx] = fmaxf(g_pN[0][idx] + g_pN[1][idx] + g_sA[r] * Wvb[n], 0.f);
}

__global__ void k_final(const float* __restrict__ Wub, const float* __restrict__ w,
                        float* __restrict__ out) {
    int r = blockIdx.x, n = threadIdx.x;
    size_t idx = (size_t)r * NH + n;
    float s = g_pO[0][idx] + g_pO[1][idx] + g_pO[2][idx] + g_pO[3][idx] + g_pO[4][idx];
    out[idx] = (s + Wub[n]) * w[r];
}

// ---------------------------------------------------------------------------
extern "C" void kernel_launch(void* const* d_in, const int* in_sizes, int n_in,
                              void* d_out, int out_size) {
    const float* X    = (const float*)d_in[0];
    const float* E    = (const float*)d_in[1];
    const float* A    = (const float*)d_in[2];
    const float* w    = (const float*)d_in[3];
    const float* Wv_w = (const float*)d_in[4];
    const float* Wv_b = (const float*)d_in[5];
    const float* We_w = (const float*)d_in[6];
    const float* We_b = (const float*)d_in[7];
    const float* Wu_w = (const float*)d_in[8];
    const float* Wu_b = (const float*)d_in[9];
    float* out = (float*)d_out;

    float *p_AtX, *p_hN, *p_hE, *p_pN, *p_pO;
    cudaGetSymbolAddress((void**)&p_AtX, g_AtX);
    cudaGetSymbolAddress((void**)&p_hN,  g_hN);
    cudaGetSymbolAddress((void**)&p_hE,  g_hE);
    cudaGetSymbolAddress((void**)&p_pN,  g_pN);
    cudaGetSymbolAddress((void**)&p_pO,  g_pO);
    float* pO0 = p_pO;                            // X branch z=0,1
    float* pO2 = p_pO + 2 * (size_t)RR * NH;      // node branch z=0,1
    float* pO4 = p_pO + 4 * (size_t)RR * NH;      // edge branch

    cudaStream_t sB, sC;
    cudaStreamCreateWithFlags(&sB, cudaStreamNonBlocking);
    cudaStreamCreateWithFlags(&sC, cudaStreamNonBlocking);
    cudaEvent_t e0, eAtx, eB, eC;
    cudaEventCreateWithFlags(&e0,   cudaEventDisableTiming);
    cudaEventCreateWithFlags(&eAtx, cudaEventDisableTiming);
    cudaEventCreateWithFlags(&eB,   cudaEventDisableTiming);
    cudaEventCreateWithFlags(&eC,   cudaEventDisableTiming);

    dim3 gP2(RR / 32, NH / 64, 2);   // (64,4,2) = 512 CTAs
    dim3 gP1(RR / 32, NH / 64, 1);   // (64,4)   = 256 CTAs
    dim3 gE (RR / 32, EH / 64);      // (64,2)

    cudaEventRecord(e0, 0);
    cudaStreamWaitEvent(sB, e0, 0);
    cudaStreamWaitEvent(sC, e0, 0);

    // sB: DRAM-bound E reduction (starts immediately, ~20+ us)
    k_agge<<<RR, 256, 0, sB>>>(A, E);

    // sC: input-independent X branch of final GEMM: relu(X) @ Wu[384:640]
    gemm_p<true><<<gP2, 128, 0, sC>>>(X, NH, 0, Wu_w, NH, 384, pO0);
    cudaEventRecord(eC, sC);

    // s0: node chain (sA folded into gemm_atx)
    gemm_atx<<<dim3(RR / 32, NH / 64), 128>>>(A, X);
    cudaEventRecord(eAtx, 0);                       // AtX + sA ready
    gemm_p<false><<<gP2, 128>>>(p_AtX, NH, 0, Wv_w, NH, 0, p_pN);
    k_reluN<<<RR, NH>>>(Wv_b);
    gemm_p<false><<<gP2, 128>>>(p_hN, NH, 0, Wu_w, NH, 0, pO2);

    // sB: edge chain (needs aggE from sB + sA from eAtx)
    cudaStreamWaitEvent(sB, eAtx, 0);
    gemm_hE<<<gE, 128, 0, sB>>>(We_w, We_b);
    gemm_p<false><<<gP1, 128, 0, sB>>>(p_hE, EH, 0, Wu_w, NH, 256, pO4);
    cudaEventRecord(eB, sB);

    // join + epilogue
    cudaStreamWaitEvent(0, eB, 0);
    cudaStreamWaitEvent(0, eC, 0);
    k_final<<<RR, NH>>>(Wu_b, w, out);

    cudaEventDestroy(e0);  cudaEventDestroy(eAtx);
    cudaEventDestroy(eB);  cudaEventDestroy(eC);
    cudaStreamDestroy(sB); cudaStreamDestroy(sC);
}

// round 5
// speedup vs baseline: 1.9706x; 1.1716x over previous
#include <cuda_runtime.h>

#define BB 16
#define MM 128
#define NH 256
#define EH 128
#define RR (BB*MM)          // 2048

// L2-resident scratch
__device__ float g_sA  [RR];
__device__ float g_aggE[RR * EH];
__device__ float g_hE  [RR * EH];
__device__ float g_pNM [2][RR * NH];   // nodeMap partials (X@Wv, K-split)
__device__ float g_pHN [2][RR * NH];   // A^T@nodeMap partials (i-split)
__device__ float g_pO  [5][RR * NH];   // final-GEMM partials

// ---------------------------------------------------------------------------
// aggE[r,e] = sum_i A[b,i,j]*E[b,i,j,e]  (streams 128MB of E once)
// also writes sA[r] = sum_i A[b,i,j]
// ---------------------------------------------------------------------------
__global__ __launch_bounds__(256) void k_agge(const float* __restrict__ A,
                                              const float* __restrict__ E) {
    int r = blockIdx.x;
    int b = r >> 7, j = r & 127;
    __shared__ float Ac[MM];
    __shared__ float red[8][EH];
    int t = threadIdx.x;
    if (t < MM) Ac[t] = A[(b * MM + t) * MM + j];
    __syncthreads();

    int lane = t & 31, grp = t >> 5;
    const float* Eb = E + ((size_t)b * MM * MM + j) * EH;
    float4 acc = {0.f, 0.f, 0.f, 0.f};
#pragma unroll
    for (int ii = 0; ii < MM; ii += 16) {
        int i0 = ii + grp, i1 = ii + 8 + grp;
        float4 v0 = *(const float4*)(Eb + (size_t)i0 * MM * EH + lane * 4);
        float4 v1 = *(const float4*)(Eb + (size_t)i1 * MM * EH + lane * 4);
        float a0 = Ac[i0], a1 = Ac[i1];
        acc.x += a0 * v0.x + a1 * v1.x;
        acc.y += a0 * v0.y + a1 * v1.y;
        acc.z += a0 * v0.z + a1 * v1.z;
        acc.w += a0 * v0.w + a1 * v1.w;
    }
    *(float4*)&red[grp][lane * 4] = acc;
    __syncthreads();
    if (t < EH) {
        float s = 0.f;
#pragma unroll
        for (int g = 0; g < 8; g++) s += red[g][t];
        g_aggE[(size_t)r * EH + t] = s;
    }
    if (t == 0) {
        float s = 0.f;
#pragma unroll
        for (int i = 0; i < MM; i++) s += Ac[i];
        g_sA[r] = s;
    }
}

// ---------------------------------------------------------------------------
// Unified GEMM: BM=64, BN=64, BK=16, 128 threads, 8x4 micro, double-buffered.
//   AMODE: 0 plain A   1 relu(A)   2 relu(A0+A1)
//   BMODE: 0 plain B   1 B0+B1+vb[col]  (combine nodeMap partials + bias)
//   EMODE: 0 store to P (+ z slot)      1 relu(acc + sA[r]*eb[col]) -> P
//   BATCH: A is per-batch k-major [b][k(i)][row(j)] (the adjacency matrix),
//          B rows also per-batch (nodeMap). Used by the hN aggregation.
// z (blockIdx.z): contiguous K chunk of KT*16; output slot offset z*pzStride.
// ---------------------------------------------------------------------------
template <int AMODE, int BMODE, int EMODE, bool BATCH>
__global__ __launch_bounds__(128) void gmm(
    const float* __restrict__ A0, const float* __restrict__ A1, int lda,
    const float* __restrict__ B0, const float* __restrict__ B1, int ldb,
    const float* __restrict__ vb, const float* __restrict__ eb,
    float* __restrict__ P, int ldp, size_t pzStride,
    int kaOff, int kbOff, int KT)
{
    __shared__ float As[2][16][68];
    __shared__ float Bs[2][16][64];

    int tid = threadIdx.x;
    int tx = tid & 15, ty = tid >> 4;
    int rowBase = blockIdx.x * 64, colBase = blockIdx.y * 64;
    int z = blockIdx.z;
    int ka = kaOff + z * KT * 16;
    int kb = kbOff + z * KT * 16;
    P += (size_t)z * pzStride;

    // ---- A pointers ----
    int kA_ = tid >> 3, rq = (tid & 7) * 8;   // batch mode
    int arow = tid >> 1, ak = (tid & 1) * 8;  // row-major mode
    const float* Ap;
    const float* Ap1 = nullptr;
    if (BATCH) {
        int b = rowBase >> 7, jloc = rowBase & 127;
        Ap = A0 + (size_t)b * MM * MM + (size_t)(ka + kA_) * MM + jloc + rq;
    } else {
        Ap = A0 + (size_t)(rowBase + arow) * lda + ka + ak;
        if (AMODE == 2) Ap1 = A1 + (size_t)(rowBase + arow) * lda + ka + ak;
    }

    // ---- B pointers ----
    int kB_ = tid >> 3, cq = (tid & 7) * 8;
    size_t bb = BATCH ? (size_t)(rowBase >> 7) * MM * ldb : 0;
    const float* Bp  = B0 + bb + (size_t)(kb + kB_) * ldb + colBase + cq;
    const float* Bp1 = (BMODE == 1) ? (B1 + bb + (size_t)(kb + kB_) * ldb + colBase + cq) : nullptr;
    float4 vb0 = {0,0,0,0}, vb1 = {0,0,0,0};
    if (BMODE == 1) {
        vb0 = *(const float4*)&vb[colBase + cq];
        vb1 = *(const float4*)&vb[colBase + cq + 4];
    }

    float acc[8][4] = {};
    float4 ra0, ra1, rb0, rb1;

    // stage-0 load
    {
        ra0 = *(const float4*)Ap; ra1 = *(const float4*)(Ap + 4);
        if (AMODE == 2) {
            float4 s0 = *(const float4*)Ap1, s1 = *(const float4*)(Ap1 + 4);
            ra0.x += s0.x; ra0.y += s0.y; ra0.z += s0.z; ra0.w += s0.w;
            ra1.x += s1.x; ra1.y += s1.y; ra1.z += s1.z; ra1.w += s1.w;
        }
        if (AMODE >= 1) {
            ra0.x = fmaxf(ra0.x, 0.f); ra0.y = fmaxf(ra0.y, 0.f);
            ra0.z = fmaxf(ra0.z, 0.f); ra0.w = fmaxf(ra0.w, 0.f);
            ra1.x = fmaxf(ra1.x, 0.f); ra1.y = fmaxf(ra1.y, 0.f);
            ra1.z = fmaxf(ra1.z, 0.f); ra1.w = fmaxf(ra1.w, 0.f);
        }
        rb0 = *(const float4*)Bp; rb1 = *(const float4*)(Bp + 4);
        if (BMODE == 1) {
            float4 s0 = *(const float4*)Bp1, s1 = *(const float4*)(Bp1 + 4);
            rb0.x += s0.x + vb0.x; rb0.y += s0.y + vb0.y;
            rb0.z += s0.z + vb0.z; rb0.w += s0.w + vb0.w;
            rb1.x += s1.x + vb1.x; rb1.y += s1.y + vb1.y;
            rb1.z += s1.z + vb1.z; rb1.w += s1.w + vb1.w;
        }
    }
    if (BATCH) {
        *(float4*)&As[0][kA_][rq] = ra0;
        *(float4*)&As[0][kA_][rq + 4] = ra1;
    } else {
        As[0][ak + 0][arow] = ra0.x; As[0][ak + 1][arow] = ra0.y;
        As[0][ak + 2][arow] = ra0.z; As[0][ak + 3][arow] = ra0.w;
        As[0][ak + 4][arow] = ra1.x; As[0][ak + 5][arow] = ra1.y;
        As[0][ak + 6][arow] = ra1.z; As[0][ak + 7][arow] = ra1.w;
    }
    *(float4*)&Bs[0][kB_][cq] = rb0;
    *(float4*)&Bs[0][kB_][cq + 4] = rb1;
    __syncthreads();

    for (int t = 0; t < KT; t++) {
        int cur = t & 1;
        bool more = (t + 1 < KT);
        if (more) {
            Ap += BATCH ? 16 * MM : 16;
            if (AMODE == 2) Ap1 += 16;
            Bp += 16 * ldb;
            if (BMODE == 1) Bp1 += 16 * ldb;
            ra0 = *(const float4*)Ap; ra1 = *(const float4*)(Ap + 4);
            if (AMODE == 2) {
                float4 s0 = *(const float4*)Ap1, s1 = *(const float4*)(Ap1 + 4);
                ra0.x += s0.x; ra0.y += s0.y; ra0.z += s0.z; ra0.w += s0.w;
                ra1.x += s1.x; ra1.y += s1.y; ra1.z += s1.z; ra1.w += s1.w;
            }
            if (AMODE >= 1) {
                ra0.x = fmaxf(ra0.x, 0.f); ra0.y = fmaxf(ra0.y, 0.f);
                ra0.z = fmaxf(ra0.z, 0.f); ra0.w = fmaxf(ra0.w, 0.f);
                ra1.x = fmaxf(ra1.x, 0.f); ra1.y = fmaxf(ra1.y, 0.f);
                ra1.z = fmaxf(ra1.z, 0.f); ra1.w = fmaxf(ra1.w, 0.f);
            }
            rb0 = *(const float4*)Bp; rb1 = *(const float4*)(Bp + 4);
            if (BMODE == 1) {
                float4 s0 = *(const float4*)Bp1, s1 = *(const float4*)(Bp1 + 4);
                rb0.x += s0.x + vb0.x; rb0.y += s0.y + vb0.y;
                rb0.z += s0.z + vb0.z; rb0.w += s0.w + vb0.w;
                rb1.x += s1.x + vb1.x; rb1.y += s1.y + vb1.y;
                rb1.z += s1.z + vb1.z; rb1.w += s1.w + vb1.w;
            }
        }
#pragma unroll
        for (int kk = 0; kk < 16; kk++) {
            float4 alo = *(const float4*)&As[cur][kk][ty * 8];
            float4 ahi = *(const float4*)&As[cur][kk][ty * 8 + 4];
            float4 b4  = *(const float4*)&Bs[cur][kk][tx * 4];
            float am[8] = {alo.x, alo.y, alo.z, alo.w, ahi.x, ahi.y, ahi.z, ahi.w};
            float bn[4] = {b4.x, b4.y, b4.z, b4.w};
#pragma unroll
            for (int i = 0; i < 8; i++)
#pragma unroll
                for (int jj = 0; jj < 4; jj++)
                    acc[i][jj] += am[i] * bn[jj];
        }
        if (more) {
            int nxt = cur ^ 1;
            if (BATCH) {
                *(float4*)&As[nxt][kA_][rq] = ra0;
                *(float4*)&As[nxt][kA_][rq + 4] = ra1;
            } else {
                As[nxt][ak + 0][arow] = ra0.x; As[nxt][ak + 1][arow] = ra0.y;
                As[nxt][ak + 2][arow] = ra0.z; As[nxt][ak + 3][arow] = ra0.w;
                As[nxt][ak + 4][arow] = ra1.x; As[nxt][ak + 5][arow] = ra1.y;
                As[nxt][ak + 6][arow] = ra1.z; As[nxt][ak + 7][arow] = ra1.w;
            }
            *(float4*)&Bs[nxt][kB_][cq] = rb0;
            *(float4*)&Bs[nxt][kB_][cq + 4] = rb1;
        }
        __syncthreads();
    }

    // epilogue
    float4 eb4 = {0,0,0,0};
    if (EMODE == 1) eb4 = *(const float4*)&eb[colBase + tx * 4];
#pragma unroll
    for (int i = 0; i < 8; i++) {
        int r = rowBase + ty * 8 + i;
        float4 v = {acc[i][0], acc[i][1], acc[i][2], acc[i][3]};
        if (EMODE == 1) {
            float sa = g_sA[r];
            v.x = fmaxf(v.x + sa * eb4.x, 0.f);
            v.y = fmaxf(v.y + sa * eb4.y, 0.f);
            v.z = fmaxf(v.z + sa * eb4.z, 0.f);
            v.w = fmaxf(v.w + sa * eb4.w, 0.f);
        }
        *(float4*)&P[(size_t)r * ldp + colBase + tx * 4] = v;
    }
}

// ---------------------------------------------------------------------------
// final: out = (pO0+pO1+pO2+pO3+pO4 + Wu_b[n]) * w[r]
// ---------------------------------------------------------------------------
__global__ void k_final(const float* __restrict__ Wub, const float* __restrict__ w,
                        float* __restrict__ out) {
    int r = blockIdx.x, n = threadIdx.x;
    size_t idx = (size_t)r * NH + n;
    float s = g_pO[0][idx] + g_pO[1][idx] + g_pO[2][idx] + g_pO[3][idx] + g_pO[4][idx];
    out[idx] = (s + Wub[n]) * w[r];
}

// ---------------------------------------------------------------------------
extern "C" void kernel_launch(void* const* d_in, const int* in_sizes, int n_in,
                              void* d_out, int out_size) {
    const float* X    = (const float*)d_in[0];
    const float* E    = (const float*)d_in[1];
    const float* A    = (const float*)d_in[2];
    const float* w    = (const float*)d_in[3];
    const float* Wv_w = (const float*)d_in[4];
    const float* Wv_b = (const float*)d_in[5];
    const float* We_w = (const float*)d_in[6];
    const float* We_b = (const float*)d_in[7];
    const float* Wu_w = (const float*)d_in[8];
    const float* Wu_b = (const float*)d_in[9];
    float* out = (float*)d_out;

    float *p_aggE, *p_hE, *p_pNM, *p_pHN, *p_pO;
    cudaGetSymbolAddress((void**)&p_aggE, g_aggE);
    cudaGetSymbolAddress((void**)&p_hE,   g_hE);
    cudaGetSymbolAddress((void**)&p_pNM,  g_pNM);
    cudaGetSymbolAddress((void**)&p_pHN,  g_pHN);
    cudaGetSymbolAddress((void**)&p_pO,   g_pO);
    const size_t SL = (size_t)RR * NH;
    float* pNM0 = p_pNM;
    float* pNM1 = p_pNM + SL;
    float* pHN0 = p_pHN;
    float* pHN1 = p_pHN + SL;

    cudaStream_t sB, sC;
    cudaStreamCreateWithFlags(&sB, cudaStreamNonBlocking);
    cudaStreamCreateWithFlags(&sC, cudaStreamNonBlocking);
    cudaEvent_t e0, eB, eC;
    cudaEventCreateWithFlags(&e0, cudaEventDisableTiming);
    cudaEventCreateWithFlags(&eB, cudaEventDisableTiming);
    cudaEventCreateWithFlags(&eC, cudaEventDisableTiming);

    dim3 g442(RR / 64, NH / 64, 2);   // (32,4,2)
    dim3 g441(RR / 64, NH / 64, 1);   // (32,4)
    dim3 g421(RR / 64, EH / 64, 1);   // (32,2)

    cudaEventRecord(e0, 0);
    cudaStreamWaitEvent(sB, e0, 0);
    cudaStreamWaitEvent(sC, e0, 0);

    // ---- sB: edge chain (fully independent until final) ----
    k_agge<<<RR, 256, 0, sB>>>(A, E);
    // hE = relu(aggE @ We + sA*We_b)
    gmm<0,0,1,false><<<g421, 128, 0, sB>>>(p_aggE, nullptr, EH, We_w, nullptr, EH,
                                           nullptr, We_b, p_hE, EH, 0, 0, 0, 8);
    // pO[4] = hE @ Wu[256:384]
    gmm<0,0,0,false><<<g441, 128, 0, sB>>>(p_hE, nullptr, EH, Wu_w, nullptr, NH,
                                           nullptr, nullptr, p_pO + 4 * SL, NH, 0, 0, 256, 8);
    cudaEventRecord(eB, sB);

    // ---- sC: X branch of final GEMM: relu(X) @ Wu[384:640] -> pO[2],pO[3] ----
    gmm<1,0,0,false><<<g442, 128, 0, sC>>>(X, nullptr, NH, Wu_w, nullptr, NH,
                                           nullptr, nullptr, p_pO + 2 * SL, NH, SL, 0, 384, 8);
    cudaEventRecord(eC, sC);

    // ---- s0: node chain ----
    // nodeMap partials: X @ Wv (K=256, z-split)
    gmm<0,0,0,false><<<g442, 128>>>(X, nullptr, NH, Wv_w, nullptr, NH,
                                    nullptr, nullptr, p_pNM, NH, SL, 0, 0, 8);
    // hN partials: A^T @ (pNM0+pNM1+Wv_b)  (per-batch, K=i split in 2)
    gmm<0,1,0,true><<<g442, 128>>>(A, nullptr, MM, pNM0, pNM1, NH,
                                   Wv_b, nullptr, p_pHN, NH, SL, 0, 0, 4);
    // pO[0],pO[1] = relu(pHN0+pHN1) @ Wu[0:256] (K=256, z-split)
    gmm<2,0,0,false><<<g442, 128>>>(pHN0, pHN1, NH, Wu_w, nullptr, NH,
                                    nullptr, nullptr, p_pO, NH, SL, 0, 0, 8);

    // ---- join + epilogue ----
    cudaStreamWaitEvent(0, eB, 0);
    cudaStreamWaitEvent(0, eC, 0);
    k_final<<<RR, NH>>>(Wu_b, w, out);

    cudaEventDestroy(e0); cudaEventDestroy(eB); cudaEventDestroy(eC);
    cudaStreamDestroy(sB); cudaStreamDestroy(sC);
}